// round 1
// baseline (speedup 1.0000x reference)
#include <cuda_runtime.h>
#include <cuda_bf16.h>
#include <math.h>

#define NN   8192
#define EE   98304
#define ET   106496          /* EE + NN self loops */
#define HID  1024
#define CC   256
#define H1   4

/* ---------------- scratch (static device memory, no allocs) ---------------- */
__device__ float g_xl1[(size_t)NN * HID];    /* X @ Wl1  [N, 4*256] */
__device__ float g_xr1[(size_t)NN * HID];    /* X @ Wr1 */
__device__ float g_x2 [(size_t)NN * HID];    /* layer-1 output (post ReLU) */
__device__ float g_xl2[(size_t)NN * CC];
__device__ float g_xr2[(size_t)NN * CC];
__device__ float g_ex1[(size_t)ET * H1];     /* exp(score) layer 1 */
__device__ float g_ex2[(size_t)ET];          /* exp(score) layer 2 */
__device__ int   g_counts [NN];
__device__ int   g_offsets[NN + 1];
__device__ int   g_cursor [NN];
__device__ int   g_csr    [ET];              /* incoming-edge ids per dst */

/* ---------------- CSR build ---------------- */
__global__ void k_init_counts() {
    int n = blockIdx.x * blockDim.x + threadIdx.x;
    if (n < NN) g_counts[n] = 1;             /* self loop pre-counted */
}

__global__ void k_count(const int* __restrict__ ei) {
    int e = blockIdx.x * blockDim.x + threadIdx.x;
    if (e < EE) atomicAdd(&g_counts[ei[EE + e]], 1);
}

__global__ void k_scan() {                   /* single block, 1024 threads, 8 items each */
    __shared__ int warp_sums[32];
    int t = threadIdx.x;
    int base = t * 8;
    int v[8];
    int s = 0;
#pragma unroll
    for (int i = 0; i < 8; i++) { v[i] = g_counts[base + i]; s += v[i]; }
    int lane = t & 31, w = t >> 5;
    int ps = s;
#pragma unroll
    for (int o = 1; o < 32; o <<= 1) {
        int x = __shfl_up_sync(0xffffffffu, ps, o);
        if (lane >= o) ps += x;
    }
    if (lane == 31) warp_sums[w] = ps;
    __syncthreads();
    if (w == 0) {
        int x = warp_sums[lane];
#pragma unroll
        for (int o = 1; o < 32; o <<= 1) {
            int y = __shfl_up_sync(0xffffffffu, x, o);
            if (lane >= o) x += y;
        }
        warp_sums[lane] = x;
    }
    __syncthreads();
    int excl = ps - s + (w > 0 ? warp_sums[w - 1] : 0);
    int run = excl;
#pragma unroll
    for (int i = 0; i < 8; i++) {
        g_offsets[base + i] = run;
        g_cursor [base + i] = run;
        run += v[i];
    }
    if (t == 1023) g_offsets[NN] = run;
}

__global__ void k_fill(const int* __restrict__ ei) {
    int idx = blockIdx.x * blockDim.x + threadIdx.x;
    if (idx >= ET) return;
    int dst = (idx < EE) ? ei[EE + idx] : (idx - EE);
    int pos = atomicAdd(&g_cursor[dst], 1);
    g_csr[pos] = idx;
}

/* ---------------- fp32 tiled GEMM: C[M,N] = A[M,K] @ B[K,N] (all row-major) --- */
#define BM 128
#define BN 128
#define BK 16

__global__ __launch_bounds__(256, 2)
void k_gemm(const float* __restrict__ A, const float* __restrict__ B,
            float* __restrict__ C, int M, int N, int K)
{
    __shared__ float As[BK][BM];
    __shared__ float Bs[BK][BN];
    const int tid = threadIdx.x;
    const int tx = tid & 15;         /* 0..15 -> col group */
    const int ty = tid >> 4;         /* 0..15 -> row group */
    const int row0 = blockIdx.y * BM;
    const int col0 = blockIdx.x * BN;

    const float* Ap = A + (size_t)row0 * K;
    const float* Bp = B + col0;

    float acc[8][8];
#pragma unroll
    for (int i = 0; i < 8; i++)
#pragma unroll
        for (int j = 0; j < 8; j++) acc[i][j] = 0.f;

    for (int k0 = 0; k0 < K; k0 += BK) {
        /* A tile: 128x16 floats = 512 float4; 2 per thread; store transposed */
#pragma unroll
        for (int i = 0; i < 2; i++) {
            int lin = tid + i * 256;
            int r  = lin >> 2;
            int c4 = (lin & 3) * 4;
            float4 v = *(const float4*)(Ap + (size_t)r * K + k0 + c4);
            As[c4 + 0][r] = v.x;
            As[c4 + 1][r] = v.y;
            As[c4 + 2][r] = v.z;
            As[c4 + 3][r] = v.w;
        }
        /* B tile: 16x128 floats = 512 float4 */
#pragma unroll
        for (int i = 0; i < 2; i++) {
            int lin = tid + i * 256;
            int r  = lin >> 5;
            int c4 = (lin & 31) * 4;
            float4 v = *(const float4*)(Bp + (size_t)(k0 + r) * N + c4);
            *(float4*)&Bs[r][c4] = v;
        }
        __syncthreads();
#pragma unroll
        for (int k = 0; k < BK; k++) {
            float a[8], b[8];
            float4 a0 = *(const float4*)&As[k][ty * 8];
            float4 a1 = *(const float4*)&As[k][ty * 8 + 4];
            float4 b0 = *(const float4*)&Bs[k][tx * 8];
            float4 b1 = *(const float4*)&Bs[k][tx * 8 + 4];
            a[0]=a0.x; a[1]=a0.y; a[2]=a0.z; a[3]=a0.w;
            a[4]=a1.x; a[5]=a1.y; a[6]=a1.z; a[7]=a1.w;
            b[0]=b0.x; b[1]=b0.y; b[2]=b0.z; b[3]=b0.w;
            b[4]=b1.x; b[5]=b1.y; b[6]=b1.z; b[7]=b1.w;
#pragma unroll
            for (int i = 0; i < 8; i++)
#pragma unroll
                for (int j = 0; j < 8; j++) acc[i][j] = fmaf(a[i], b[j], acc[i][j]);
        }
        __syncthreads();
    }
#pragma unroll
    for (int i = 0; i < 8; i++) {
        float* cp = C + (size_t)(row0 + ty * 8 + i) * N + col0 + tx * 8;
        *(float4*)(cp)     = make_float4(acc[i][0], acc[i][1], acc[i][2], acc[i][3]);
        *(float4*)(cp + 4) = make_float4(acc[i][4], acc[i][5], acc[i][6], acc[i][7]);
    }
}

/* ---------------- layer-1 edge scores: warp per edge, 4 heads ---------------- */
__global__ void k_score1(const int* __restrict__ ei, const float* __restrict__ att)
{
    int e = (blockIdx.x * blockDim.x + threadIdx.x) >> 5;
    if (e >= ET) return;
    int lane = threadIdx.x & 31;
    int s = (e < EE) ? ei[e]      : (e - EE);
    int d = (e < EE) ? ei[EE + e] : (e - EE);
    const float* xs = g_xl1 + (size_t)s * HID;
    const float* xd = g_xr1 + (size_t)d * HID;
#pragma unroll
    for (int h = 0; h < H1; h++) {
        float acc = 0.f;
#pragma unroll
        for (int i = 0; i < 8; i++) {
            int c = h * CC + i * 32 + lane;
            float v = xs[c] + xd[c];
            v = (v > 0.f) ? v : 0.2f * v;
            acc += v * att[c];
        }
#pragma unroll
        for (int o = 16; o > 0; o >>= 1)
            acc += __shfl_xor_sync(0xffffffffu, acc, o);
        if (lane == 0) g_ex1[(size_t)e * H1 + h] = expf(acc);
    }
}

/* ---- layer-1 aggregate + bias + ReLU: block per (node, head), 256 threads --- */
__global__ void k_agg1(const int* __restrict__ ei, const float* __restrict__ bias)
{
    int n = blockIdx.x >> 2;
    int h = blockIdx.x & 3;
    int c = threadIdx.x;
    int beg = g_offsets[n], end = g_offsets[n + 1];
    float num = 0.f, den = 0.f;
    for (int j = beg; j < end; j++) {
        int e = g_csr[j];
        int s = (e < EE) ? ei[e] : (e - EE);
        float ex = g_ex1[(size_t)e * H1 + h];
        num = fmaf(ex, g_xl1[(size_t)s * HID + h * CC + c], num);
        den += ex;
    }
    float r = num / den + bias[h * CC + c];
    g_x2[(size_t)n * HID + h * CC + c] = fmaxf(r, 0.f);
}

/* ---------------- layer-2 edge scores: warp per edge, 1 head ----------------- */
__global__ void k_score2(const int* __restrict__ ei, const float* __restrict__ att)
{
    int e = (blockIdx.x * blockDim.x + threadIdx.x) >> 5;
    if (e >= ET) return;
    int lane = threadIdx.x & 31;
    int s = (e < EE) ? ei[e]      : (e - EE);
    int d = (e < EE) ? ei[EE + e] : (e - EE);
    const float* xs = g_xl2 + (size_t)s * CC;
    const float* xd = g_xr2 + (size_t)d * CC;
    float acc = 0.f;
#pragma unroll
    for (int i = 0; i < 8; i++) {
        int c = i * 32 + lane;
        float v = xs[c] + xd[c];
        v = (v > 0.f) ? v : 0.2f * v;
        acc += v * att[c];
    }
#pragma unroll
    for (int o = 16; o > 0; o >>= 1)
        acc += __shfl_xor_sync(0xffffffffu, acc, o);
    if (lane == 0) g_ex2[e] = expf(acc);
}

/* ---- layer-2 aggregate + bias + ReLU -> d_out ---- */
__global__ void k_agg2(const int* __restrict__ ei, const float* __restrict__ bias,
                       float* __restrict__ out)
{
    int n = blockIdx.x;
    int c = threadIdx.x;
    int beg = g_offsets[n], end = g_offsets[n + 1];
    float num = 0.f, den = 0.f;
    for (int j = beg; j < end; j++) {
        int e = g_csr[j];
        int s = (e < EE) ? ei[e] : (e - EE);
        float ex = g_ex2[e];
        num = fmaf(ex, g_xl2[(size_t)s * CC + c], num);
        den += ex;
    }
    float r = num / den + bias[c];
    out[(size_t)n * CC + c] = fmaxf(r, 0.f);
}

/* ---------------- launch ---------------- */
extern "C" void kernel_launch(void* const* d_in, const int* in_sizes, int n_in,
                              void* d_out, int out_size)
{
    const float* x    = (const float*)d_in[0];
    const int*   ei   = (const int*)  d_in[1];
    const float* Wl1  = (const float*)d_in[2];
    const float* Wr1  = (const float*)d_in[3];
    const float* att1 = (const float*)d_in[4];
    const float* b1   = (const float*)d_in[5];
    const float* Wl2  = (const float*)d_in[6];
    const float* Wr2  = (const float*)d_in[7];
    const float* att2 = (const float*)d_in[8];
    const float* b2   = (const float*)d_in[9];
    float* out = (float*)d_out;

    float *p_xl1, *p_xr1, *p_x2, *p_xl2, *p_xr2;
    cudaGetSymbolAddress((void**)&p_xl1, g_xl1);
    cudaGetSymbolAddress((void**)&p_xr1, g_xr1);
    cudaGetSymbolAddress((void**)&p_x2,  g_x2);
    cudaGetSymbolAddress((void**)&p_xl2, g_xl2);
    cudaGetSymbolAddress((void**)&p_xr2, g_xr2);

    /* CSR build */
    k_init_counts<<<NN / 256, 256>>>();
    k_count<<<EE / 256, 256>>>(ei);
    k_scan<<<1, 1024>>>();
    k_fill<<<ET / 256, 256>>>(ei);

    /* layer 1 */
    k_gemm<<<dim3(HID / BN, NN / BM), 256>>>(x, Wl1, p_xl1, NN, HID, HID);
    k_gemm<<<dim3(HID / BN, NN / BM), 256>>>(x, Wr1, p_xr1, NN, HID, HID);
    k_score1<<<ET / 8, 256>>>(ei, att1);
    k_agg1<<<NN * H1, 256>>>(ei, b1);

    /* layer 2 */
    k_gemm<<<dim3(CC / BN, NN / BM), 256>>>(p_x2, Wl2, p_xl2, NN, CC, HID);
    k_gemm<<<dim3(CC / BN, NN / BM), 256>>>(p_x2, Wr2, p_xr2, NN, CC, HID);
    k_score2<<<ET / 8, 256>>>(ei, att2);
    k_agg2<<<NN, 256>>>(ei, b2, out);
}

// round 3
// speedup vs baseline: 1.9681x; 1.9681x over previous
#include <cuda_runtime.h>
#include <cuda_bf16.h>
#include <math.h>
#include <stdint.h>

#define NN   8192
#define EE   98304
#define ET   106496          /* EE + NN self loops */
#define K1   1024            /* inner dim of both GEMMs */
#define CC   256
#define H1   4
#define NT1  2048            /* layer-1 combined output cols (xl|xr) */
#define NT2  512             /* layer-2 combined output cols */

/* ---------------- scratch (static device memory, no allocs) ---------------- */
__device__ __nv_bfloat16 g_Ax1[(size_t)NN * 2 * K1];   /* X split [hi|lo]   */
__device__ __nv_bfloat16 g_Bt1[(size_t)NT1 * 2 * K1];  /* [Wl1|Wr1]^T split */
__device__ float         g_C1 [(size_t)NN * NT1];      /* xl1|xr1           */
__device__ __nv_bfloat16 g_Ax2[(size_t)NN * 2 * K1];   /* layer-1 out split */
__device__ __nv_bfloat16 g_Bt2[(size_t)NT2 * 2 * K1];  /* [Wl2|Wr2]^T split */
__device__ float         g_C2 [(size_t)NN * NT2];      /* xl2|xr2           */
__device__ float g_ex1[(size_t)ET * H1];
__device__ float g_ex2[(size_t)ET];
__device__ int   g_counts [NN];
__device__ int   g_offsets[NN + 1];
__device__ int   g_cursor [NN];
__device__ int   g_csr    [ET];

/* ---------------- PTX helpers ---------------- */
__device__ __forceinline__ uint32_t smem_u32(const void* p) {
    uint32_t a;
    asm("{ .reg .u64 t; cvta.to.shared.u64 t, %1; cvt.u32.u64 %0, t; }" : "=r"(a) : "l"(p));
    return a;
}
#define CP16(dst, src) asm volatile("cp.async.cg.shared.global [%0], [%1], 16;" :: "r"(dst), "l"(src) : "memory")
#define CP_COMMIT()    asm volatile("cp.async.commit_group;" ::: "memory")

__device__ __forceinline__ void ldsm4(uint32_t* r, uint32_t addr) {
    asm volatile("ldmatrix.sync.aligned.m8n8.x4.shared.b16 {%0,%1,%2,%3}, [%4];"
        : "=r"(r[0]), "=r"(r[1]), "=r"(r[2]), "=r"(r[3]) : "r"(addr));
}
__device__ __forceinline__ void mma16816(float* c, const uint32_t* a, const uint32_t* b) {
    asm volatile(
        "mma.sync.aligned.m16n8k16.row.col.f32.bf16.bf16.f32 "
        "{%0,%1,%2,%3}, {%4,%5,%6,%7}, {%8,%9}, {%0,%1,%2,%3};"
        : "+f"(c[0]), "+f"(c[1]), "+f"(c[2]), "+f"(c[3])
        : "r"(a[0]), "r"(a[1]), "r"(a[2]), "r"(a[3]), "r"(b[0]), "r"(b[1]));
}

/* ---------------- CSR build ---------------- */
__global__ void k_init_counts() {
    int n = blockIdx.x * blockDim.x + threadIdx.x;
    if (n < NN) g_counts[n] = 1;
}
__global__ void k_count(const int* __restrict__ ei) {
    int e = blockIdx.x * blockDim.x + threadIdx.x;
    if (e < EE) atomicAdd(&g_counts[ei[EE + e]], 1);
}
__global__ void k_scan() {
    __shared__ int warp_sums[32];
    int t = threadIdx.x, base = t * 8, v[8], s = 0;
#pragma unroll
    for (int i = 0; i < 8; i++) { v[i] = g_counts[base + i]; s += v[i]; }
    int lane = t & 31, w = t >> 5, ps = s;
#pragma unroll
    for (int o = 1; o < 32; o <<= 1) {
        int x = __shfl_up_sync(0xffffffffu, ps, o);
        if (lane >= o) ps += x;
    }
    if (lane == 31) warp_sums[w] = ps;
    __syncthreads();
    if (w == 0) {
        int x = warp_sums[lane];
#pragma unroll
        for (int o = 1; o < 32; o <<= 1) {
            int y = __shfl_up_sync(0xffffffffu, x, o);
            if (lane >= o) x += y;
        }
        warp_sums[lane] = x;
    }
    __syncthreads();
    int run = ps - s + (w > 0 ? warp_sums[w - 1] : 0);
#pragma unroll
    for (int i = 0; i < 8; i++) {
        g_offsets[base + i] = run;
        g_cursor [base + i] = run;
        run += v[i];
    }
    if (t == 1023) g_offsets[NN] = run;
}
__global__ void k_fill(const int* __restrict__ ei) {
    int idx = blockIdx.x * blockDim.x + threadIdx.x;
    if (idx >= ET) return;
    int dst = (idx < EE) ? ei[EE + idx] : (idx - EE);
    g_csr[atomicAdd(&g_cursor[dst], 1)] = idx;
}

/* ---------------- bf16 hi/lo splits ---------------- */
__global__ void k_split_x(const float* __restrict__ X) {
    int idx = blockIdx.x * blockDim.x + threadIdx.x;   /* NN*K1 threads */
    int r = idx >> 10, k = idx & 1023;
    float v = X[idx];
    __nv_bfloat16 h = __float2bfloat16(v);
    g_Ax1[(size_t)r * 2048 + k]        = h;
    g_Ax1[(size_t)r * 2048 + 1024 + k] = __float2bfloat16(v - __bfloat162float(h));
}

/* transpose + split: W [K1, Nout] -> Bt rows (n_off..), cols [hi(0..K1)|lo] */
__global__ void k_split_w(const float* __restrict__ W, __nv_bfloat16* __restrict__ Bt,
                          int Nout, int n_off) {
    __shared__ float t[32][33];
    int nx = blockIdx.x * 32, kx = blockIdx.y * 32;
    int tx = threadIdx.x, ty = threadIdx.y;
#pragma unroll
    for (int i = 0; i < 32; i += 8)
        t[ty + i][tx] = W[(size_t)(kx + ty + i) * Nout + nx + tx];
    __syncthreads();
#pragma unroll
    for (int i = 0; i < 32; i += 8) {
        float v = t[tx][ty + i];
        int n = n_off + nx + ty + i, k = kx + tx;
        __nv_bfloat16 h = __float2bfloat16(v);
        Bt[(size_t)n * 2048 + k]        = h;
        Bt[(size_t)n * 2048 + 1024 + k] = __float2bfloat16(v - __bfloat162float(h));
    }
}

/* ---------------- mma.sync split-bf16 GEMM ----------------
   C[M, Ntot] = A3 @ B3^T, virtual K3 = 3*K1 over hi/lo storage [., 2*K1].
   CTA tile 128x128, 8 warps of 64x32, BK=32, 3-stage cp.async pipeline.   */
#define BM   128
#define BN   128
#define BK   32
#define NST  3
#define NIT  96                  /* 3*K1 / BK */
#define STR  20                  /* u32 stride per row (16 kpairs + 4 pad) */
#define A_U32 (BM * STR)
#define B_U32 (BN * STR)
#define STAGE_BYTES ((A_U32 + B_U32) * 4)
#define GEMM_SMEM (NST * STAGE_BYTES)

__global__ void __launch_bounds__(256, 2)
k_gemm_tc(const __nv_bfloat16* __restrict__ A, const __nv_bfloat16* __restrict__ B,
          float* __restrict__ C, int Ntot)
{
    extern __shared__ char smem[];
    const uint32_t sb = smem_u32(smem);
    const int tid = threadIdx.x;
    const int lane = tid & 31;
    const int w = tid >> 5;
    const int wm = (w & 1) * 64;       /* warp m offset in tile */
    const int wn = (w >> 1) * 32;      /* warp n offset in tile */
    const int row0 = blockIdx.y * BM;
    const int col0 = blockIdx.x * BN;
    const int K2 = 2 * K1;

    float acc[4][4][4];
#pragma unroll
    for (int i = 0; i < 4; i++)
#pragma unroll
        for (int j = 0; j < 4; j++)
#pragma unroll
            for (int q = 0; q < 4; q++) acc[i][j][q] = 0.f;

    /* ldmatrix per-lane invariants */
    const int msel = lane >> 3, within = lane & 7;
    const int a_r = (msel & 1) * 8 + within;       /* row within mf tile  */
    const int a_c = (msel >> 1) * 4;               /* u32 col within kstep */
    const int b_r = (msel >> 1) * 8 + within;      /* row within nf pair  */
    const int b_c = (msel & 1) * 4;

    auto load_chunk = [&](int ch) {
        int k0v = ch * BK;
        int a_k0 = k0v - (k0v >= K1 ? K1 : 0);
        int b_k0 = k0v - (k0v >= 2 * K1 ? 2 * K1 : 0);
        uint32_t sa = sb + (ch % NST) * STAGE_BYTES;
        uint32_t sB = sa + A_U32 * 4;
#pragma unroll
        for (int i = 0; i < 2; i++) {
            int lin = tid + i * 256, r = lin >> 2, j = lin & 3;
            CP16(sa + r * (STR * 4) + j * 16,
                 __cvta_generic_to_global(A + (size_t)(row0 + r) * K2 + a_k0 + j * 8));
        }
#pragma unroll
        for (int i = 0; i < 2; i++) {
            int lin = tid + i * 256, r = lin >> 2, j = lin & 3;
            CP16(sB + r * (STR * 4) + j * 16,
                 __cvta_generic_to_global(B + (size_t)(col0 + r) * K2 + b_k0 + j * 8));
        }
        CP_COMMIT();
    };

    load_chunk(0);
    load_chunk(1);

    for (int it = 0; it < NIT; it++) {
        if (it + 2 < NIT) load_chunk(it + 2);
        int rem = ((it + 2 < NIT) ? (it + 2) : (NIT - 1)) - it;
        if (rem == 2)      asm volatile("cp.async.wait_group 2;" ::: "memory");
        else if (rem == 1) asm volatile("cp.async.wait_group 1;" ::: "memory");
        else               asm volatile("cp.async.wait_group 0;" ::: "memory");
        __syncthreads();

        uint32_t sa = sb + (it % NST) * STAGE_BYTES;
        uint32_t sB = sa + A_U32 * 4;
#pragma unroll
        for (int kk = 0; kk < 2; kk++) {
            uint32_t af[4][4], bf[4][2];
#pragma unroll
            for (int mf = 0; mf < 4; mf++)
                ldsm4(af[mf], sa + ((wm + mf * 16 + a_r) * STR + kk * 8 + a_c) * 4);
#pragma unroll
            for (int p = 0; p < 2; p++) {
                uint32_t t4[4];
                ldsm4(t4, sB + ((wn + p * 16 + b_r) * STR + kk * 8 + b_c) * 4);
                bf[2 * p][0] = t4[0]; bf[2 * p][1] = t4[1];
                bf[2 * p + 1][0] = t4[2]; bf[2 * p + 1][1] = t4[3];
            }
#pragma unroll
            for (int mf = 0; mf < 4; mf++)
#pragma unroll
                for (int nf = 0; nf < 4; nf++)
                    mma16816(acc[mf][nf], af[mf], bf[nf]);
        }
        __syncthreads();
    }

    /* epilogue */
    const int r = lane >> 2, q = lane & 3;
#pragma unroll
    for (int mf = 0; mf < 4; mf++) {
        int rg = row0 + wm + mf * 16 + r;
#pragma unroll
        for (int nf = 0; nf < 4; nf++) {
            float* p0 = C + (size_t)rg * Ntot + col0 + wn + nf * 8 + q * 2;
            *(float2*)p0 = make_float2(acc[mf][nf][0], acc[mf][nf][1]);
            *(float2*)(p0 + (size_t)8 * Ntot) = make_float2(acc[mf][nf][2], acc[mf][nf][3]);
        }
    }
}

/* ---------------- layer-1 edge scores: warp per edge, 4 heads ---------------- */
__global__ void k_score1(const int* __restrict__ ei, const float* __restrict__ att)
{
    int e = (blockIdx.x * blockDim.x + threadIdx.x) >> 5;
    if (e >= ET) return;
    int lane = threadIdx.x & 31;
    int s = (e < EE) ? ei[e]      : (e - EE);
    int d = (e < EE) ? ei[EE + e] : (e - EE);
    const float* xs = g_C1 + (size_t)s * NT1;          /* xl cols [0,1024) */
    const float* xd = g_C1 + (size_t)d * NT1 + 1024;   /* xr cols          */
#pragma unroll
    for (int h = 0; h < H1; h++) {
        float acc = 0.f;
#pragma unroll
        for (int i = 0; i < 8; i++) {
            int c = h * CC + i * 32 + lane;
            float v = xs[c] + xd[c];
            v = (v > 0.f) ? v : 0.2f * v;
            acc += v * att[c];
        }
#pragma unroll
        for (int o = 16; o > 0; o >>= 1)
            acc += __shfl_xor_sync(0xffffffffu, acc, o);
        if (lane == 0) g_ex1[(size_t)e * H1 + h] = expf(acc);
    }
}

/* layer-1 aggregate + bias + ReLU -> bf16 hi/lo split (layer-2 A operand) */
__global__ void k_agg1(const int* __restrict__ ei, const float* __restrict__ bias)
{
    int n = blockIdx.x >> 2;
    int h = blockIdx.x & 3;
    int c = threadIdx.x;
    int col = h * CC + c;
    int beg = g_offsets[n], end = g_offsets[n + 1];
    float num = 0.f, den = 0.f;
    for (int j = beg; j < end; j++) {
        int e = g_csr[j];
        int s = (e < EE) ? ei[e] : (e - EE);
        float ex = g_ex1[(size_t)e * H1 + h];
        num = fmaf(ex, g_C1[(size_t)s * NT1 + col], num);
        den += ex;
    }
    float rv = fmaxf(num / den + bias[col], 0.f);
    __nv_bfloat16 hi = __float2bfloat16(rv);
    g_Ax2[(size_t)n * 2048 + col]        = hi;
    g_Ax2[(size_t)n * 2048 + 1024 + col] = __float2bfloat16(rv - __bfloat162float(hi));
}

/* ---------------- layer-2 edge scores: warp per edge, 1 head ----------------- */
__global__ void k_score2(const int* __restrict__ ei, const float* __restrict__ att)
{
    int e = (blockIdx.x * blockDim.x + threadIdx.x) >> 5;
    if (e >= ET) return;
    int lane = threadIdx.x & 31;
    int s = (e < EE) ? ei[e]      : (e - EE);
    int d = (e < EE) ? ei[EE + e] : (e - EE);
    const float* xs = g_C2 + (size_t)s * NT2;
    const float* xd = g_C2 + (size_t)d * NT2 + 256;
    float acc = 0.f;
#pragma unroll
    for (int i = 0; i < 8; i++) {
        int c = i * 32 + lane;
        float v = xs[c] + xd[c];
        v = (v > 0.f) ? v : 0.2f * v;
        acc += v * att[c];
    }
#pragma unroll
    for (int o = 16; o > 0; o >>= 1)
        acc += __shfl_xor_sync(0xffffffffu, acc, o);
    if (lane == 0) g_ex2[e] = expf(acc);
}

__global__ void k_agg2(const int* __restrict__ ei, const float* __restrict__ bias,
                       float* __restrict__ out)
{
    int n = blockIdx.x;
    int c = threadIdx.x;
    int beg = g_offsets[n], end = g_offsets[n + 1];
    float num = 0.f, den = 0.f;
    for (int j = beg; j < end; j++) {
        int e = g_csr[j];
        int s = (e < EE) ? ei[e] : (e - EE);
        float ex = g_ex2[e];
        num = fmaf(ex, g_C2[(size_t)s * NT2 + c], num);
        den += ex;
    }
    out[(size_t)n * CC + c] = fmaxf(num / den + bias[c], 0.f);
}

/* ---------------- launch ---------------- */
extern "C" void kernel_launch(void* const* d_in, const int* in_sizes, int n_in,
                              void* d_out, int out_size)
{
    const float* x    = (const float*)d_in[0];
    const int*   ei   = (const int*)  d_in[1];
    const float* Wl1  = (const float*)d_in[2];
    const float* Wr1  = (const float*)d_in[3];
    const float* att1 = (const float*)d_in[4];
    const float* b1   = (const float*)d_in[5];
    const float* Wl2  = (const float*)d_in[6];
    const float* Wr2  = (const float*)d_in[7];
    const float* att2 = (const float*)d_in[8];
    const float* b2   = (const float*)d_in[9];
    float* out = (float*)d_out;

    __nv_bfloat16 *p_Ax1, *p_Bt1, *p_Ax2, *p_Bt2;
    float *p_C1, *p_C2;
    cudaGetSymbolAddress((void**)&p_Ax1, g_Ax1);
    cudaGetSymbolAddress((void**)&p_Bt1, g_Bt1);
    cudaGetSymbolAddress((void**)&p_C1,  g_C1);
    cudaGetSymbolAddress((void**)&p_Ax2, g_Ax2);
    cudaGetSymbolAddress((void**)&p_Bt2, g_Bt2);
    cudaGetSymbolAddress((void**)&p_C2,  g_C2);

    cudaFuncSetAttribute(k_gemm_tc, cudaFuncAttributeMaxDynamicSharedMemorySize, GEMM_SMEM);

    /* CSR build + input splits */
    k_init_counts<<<NN / 256, 256>>>();
    k_count<<<EE / 256, 256>>>(ei);
    k_scan<<<1, 1024>>>();
    k_fill<<<ET / 256, 256>>>(ei);
    k_split_x<<<NN * K1 / 256, 256>>>(x);
    k_split_w<<<dim3(1024 / 32, K1 / 32), dim3(32, 8)>>>(Wl1, p_Bt1, 1024, 0);
    k_split_w<<<dim3(1024 / 32, K1 / 32), dim3(32, 8)>>>(Wr1, p_Bt1, 1024, 1024);
    k_split_w<<<dim3(256 / 32, K1 / 32),  dim3(32, 8)>>>(Wl2, p_Bt2, 256, 0);
    k_split_w<<<dim3(256 / 32, K1 / 32),  dim3(32, 8)>>>(Wr2, p_Bt2, 256, 256);

    /* layer 1 */
    k_gemm_tc<<<dim3(NT1 / BN, NN / BM), 256, GEMM_SMEM>>>(p_Ax1, p_Bt1, p_C1, NT1);
    k_score1<<<ET / 8, 256>>>(ei, att1);
    k_agg1<<<NN * H1, 256>>>(ei, b1);

    /* layer 2 */
    k_gemm_tc<<<dim3(NT2 / BN, NN / BM), 256, GEMM_SMEM>>>(p_Ax2, p_Bt2, p_C2, NT2);
    k_score2<<<ET / 8, 256>>>(ei, att2);
    k_agg2<<<NN, 256>>>(ei, b2, out);
}

// round 4
// speedup vs baseline: 2.5387x; 1.2899x over previous
#include <cuda_runtime.h>
#include <cuda_bf16.h>
#include <math.h>
#include <stdint.h>

#define NN   8192
#define EE   98304
#define ET   106496          /* EE + NN self loops */
#define K1   1024            /* inner dim of both GEMMs */
#define CC   256
#define NT1  2048            /* layer-1 combined output cols (xl|xr) */
#define NT2  512             /* layer-2 combined output cols */

/* ---------------- scratch (static device memory, no allocs) ---------------- */
__device__ __nv_bfloat16 g_Ax1[(size_t)NN * 2 * K1];   /* X split [hi|lo]   */
__device__ __nv_bfloat16 g_Bt1[(size_t)NT1 * 2 * K1];  /* [Wl1|Wr1]^T split */
__device__ float         g_C1 [(size_t)NN * NT1];      /* xl1|xr1           */
__device__ __nv_bfloat16 g_Ax2[(size_t)NN * 2 * K1];   /* layer-1 out split */
__device__ __nv_bfloat16 g_Bt2[(size_t)NT2 * 2 * K1];  /* [Wl2|Wr2]^T split */
__device__ float         g_C2 [(size_t)NN * NT2];      /* xl2|xr2           */
__device__ int   g_counts [NN];
__device__ int   g_offsets[NN + 1];
__device__ int   g_cursor [NN];
__device__ int   g_csr    [ET];                        /* src node per CSR slot */

/* ---------------- PTX helpers ---------------- */
__device__ __forceinline__ uint32_t smem_u32(const void* p) {
    uint32_t a;
    asm("{ .reg .u64 t; cvta.to.shared.u64 t, %1; cvt.u32.u64 %0, t; }" : "=r"(a) : "l"(p));
    return a;
}
#define CP16(dst, src) asm volatile("cp.async.cg.shared.global [%0], [%1], 16;" :: "r"(dst), "l"(src) : "memory")
#define CP_COMMIT()    asm volatile("cp.async.commit_group;" ::: "memory")

__device__ __forceinline__ void ldsm4(uint32_t* r, uint32_t addr) {
    asm volatile("ldmatrix.sync.aligned.m8n8.x4.shared.b16 {%0,%1,%2,%3}, [%4];"
        : "=r"(r[0]), "=r"(r[1]), "=r"(r[2]), "=r"(r[3]) : "r"(addr));
}
__device__ __forceinline__ void mma16816(float* c, const uint32_t* a, const uint32_t* b) {
    asm volatile(
        "mma.sync.aligned.m16n8k16.row.col.f32.bf16.bf16.f32 "
        "{%0,%1,%2,%3}, {%4,%5,%6,%7}, {%8,%9}, {%0,%1,%2,%3};"
        : "+f"(c[0]), "+f"(c[1]), "+f"(c[2]), "+f"(c[3])
        : "r"(a[0]), "r"(a[1]), "r"(a[2]), "r"(a[3]), "r"(b[0]), "r"(b[1]));
}

/* ---------------- CSR build ---------------- */
__global__ void k_init_counts() {
    int n = blockIdx.x * blockDim.x + threadIdx.x;
    if (n < NN) g_counts[n] = 1;
}
__global__ void k_count(const int* __restrict__ ei) {
    int e = blockIdx.x * blockDim.x + threadIdx.x;
    if (e < EE) atomicAdd(&g_counts[ei[EE + e]], 1);
}
__global__ void k_scan() {
    __shared__ int warp_sums[32];
    int t = threadIdx.x, base = t * 8, v[8], s = 0;
#pragma unroll
    for (int i = 0; i < 8; i++) { v[i] = g_counts[base + i]; s += v[i]; }
    int lane = t & 31, w = t >> 5, ps = s;
#pragma unroll
    for (int o = 1; o < 32; o <<= 1) {
        int x = __shfl_up_sync(0xffffffffu, ps, o);
        if (lane >= o) ps += x;
    }
    if (lane == 31) warp_sums[w] = ps;
    __syncthreads();
    if (w == 0) {
        int x = warp_sums[lane];
#pragma unroll
        for (int o = 1; o < 32; o <<= 1) {
            int y = __shfl_up_sync(0xffffffffu, x, o);
            if (lane >= o) x += y;
        }
        warp_sums[lane] = x;
    }
    __syncthreads();
    int run = ps - s + (w > 0 ? warp_sums[w - 1] : 0);
#pragma unroll
    for (int i = 0; i < 8; i++) {
        g_offsets[base + i] = run;
        g_cursor [base + i] = run;
        run += v[i];
    }
    if (t == 1023) g_offsets[NN] = run;
}
__global__ void k_fill(const int* __restrict__ ei) {
    int idx = blockIdx.x * blockDim.x + threadIdx.x;
    if (idx >= ET) return;
    int src, dst;
    if (idx < EE) { src = ei[idx]; dst = ei[EE + idx]; }
    else          { src = dst = idx - EE; }
    g_csr[atomicAdd(&g_cursor[dst], 1)] = src;
}

/* ---------------- bf16 hi/lo splits ---------------- */
__global__ void k_split_x(const float* __restrict__ X) {
    int idx = blockIdx.x * blockDim.x + threadIdx.x;   /* NN*K1/4 threads */
    int r = idx >> 8, kq = idx & 255;
    float4 v = *(const float4*)(X + ((size_t)r << 10) + kq * 4);
    __nv_bfloat16 h0 = __float2bfloat16(v.x), h1 = __float2bfloat16(v.y);
    __nv_bfloat16 h2 = __float2bfloat16(v.z), h3 = __float2bfloat16(v.w);
    size_t base = (size_t)r * 2048 + kq * 4;
    *(__nv_bfloat162*)&g_Ax1[base]     = __nv_bfloat162(h0, h1);
    *(__nv_bfloat162*)&g_Ax1[base + 2] = __nv_bfloat162(h2, h3);
    *(__nv_bfloat162*)&g_Ax1[base + 1024] = __nv_bfloat162(
        __float2bfloat16(v.x - __bfloat162float(h0)), __float2bfloat16(v.y - __bfloat162float(h1)));
    *(__nv_bfloat162*)&g_Ax1[base + 1026] = __nv_bfloat162(
        __float2bfloat16(v.z - __bfloat162float(h2)), __float2bfloat16(v.w - __bfloat162float(h3)));
}

/* transpose + split: W [K1, Nout] -> Bt rows (n_off..), cols [hi(0..K1)|lo] */
__global__ void k_split_w(const float* __restrict__ W, __nv_bfloat16* __restrict__ Bt,
                          int Nout, int n_off) {
    __shared__ float t[32][33];
    int nx = blockIdx.x * 32, kx = blockIdx.y * 32;
    int tx = threadIdx.x, ty = threadIdx.y;
#pragma unroll
    for (int i = 0; i < 32; i += 8)
        t[ty + i][tx] = W[(size_t)(kx + ty + i) * Nout + nx + tx];
    __syncthreads();
#pragma unroll
    for (int i = 0; i < 32; i += 8) {
        float v = t[tx][ty + i];
        int n = n_off + nx + ty + i, k = kx + tx;
        __nv_bfloat16 h = __float2bfloat16(v);
        Bt[(size_t)n * 2048 + k]        = h;
        Bt[(size_t)n * 2048 + 1024 + k] = __float2bfloat16(v - __bfloat162float(h));
    }
}

/* ---------------- mma.sync split-bf16 GEMM ----------------
   C[M, Ntot] = A3 @ B3^T, virtual K3 = 3*K1 over hi/lo storage [., 2*K1].
   CTA tile 128x128, 8 warps of 64x32, BK=32, 4-stage, one sync per iter.  */
#define BM   128
#define BN   128
#define BK   32
#define NST  4
#define NIT  96                  /* 3*K1 / BK */
#define STR  20                  /* u32 stride per row (16 kpairs + 4 pad) */
#define A_U32 (BM * STR)
#define B_U32 (BN * STR)
#define STAGE_BYTES ((A_U32 + B_U32) * 4)
#define GEMM_SMEM (NST * STAGE_BYTES)

__global__ void __launch_bounds__(256, 2)
k_gemm_tc(const __nv_bfloat16* __restrict__ A, const __nv_bfloat16* __restrict__ B,
          float* __restrict__ C, int Ntot)
{
    extern __shared__ char smem[];
    const uint32_t sb = smem_u32(smem);
    const int tid = threadIdx.x;
    const int lane = tid & 31;
    const int w = tid >> 5;
    const int wm = (w & 1) * 64;
    const int wn = (w >> 1) * 32;
    const int row0 = blockIdx.y * BM;
    const int col0 = blockIdx.x * BN;
    const int K2 = 2 * K1;

    float acc[4][4][4];
#pragma unroll
    for (int i = 0; i < 4; i++)
#pragma unroll
        for (int j = 0; j < 4; j++)
#pragma unroll
            for (int q = 0; q < 4; q++) acc[i][j][q] = 0.f;

    const int msel = lane >> 3, within = lane & 7;
    const int a_r = (msel & 1) * 8 + within;
    const int a_c = (msel >> 1) * 4;
    const int b_r = (msel >> 1) * 8 + within;
    const int b_c = (msel & 1) * 4;

    auto load_chunk = [&](int ch) {
        int k0v = ch * BK;
        int a_k0 = k0v - (k0v >= K1 ? K1 : 0);
        int b_k0 = k0v - (k0v >= 2 * K1 ? 2 * K1 : 0);
        uint32_t sa = sb + (ch % NST) * STAGE_BYTES;
        uint32_t sB = sa + A_U32 * 4;
#pragma unroll
        for (int i = 0; i < 2; i++) {
            int lin = tid + i * 256, r = lin >> 2, j = lin & 3;
            CP16(sa + r * (STR * 4) + j * 16,
                 __cvta_generic_to_global(A + (size_t)(row0 + r) * K2 + a_k0 + j * 8));
        }
#pragma unroll
        for (int i = 0; i < 2; i++) {
            int lin = tid + i * 256, r = lin >> 2, j = lin & 3;
            CP16(sB + r * (STR * 4) + j * 16,
                 __cvta_generic_to_global(B + (size_t)(col0 + r) * K2 + b_k0 + j * 8));
        }
        CP_COMMIT();
    };

    load_chunk(0); load_chunk(1); load_chunk(2);

    for (int it = 0; it < NIT; it++) {
        if (it < NIT - 2)       asm volatile("cp.async.wait_group 2;" ::: "memory");
        else if (it == NIT - 2) asm volatile("cp.async.wait_group 1;" ::: "memory");
        else                    asm volatile("cp.async.wait_group 0;" ::: "memory");
        __syncthreads();
        if (it + NST - 1 < NIT) load_chunk(it + NST - 1);

        uint32_t sa = sb + (it % NST) * STAGE_BYTES;
        uint32_t sB = sa + A_U32 * 4;
#pragma unroll
        for (int kk = 0; kk < 2; kk++) {
            uint32_t af[4][4], bf[4][2];
#pragma unroll
            for (int mf = 0; mf < 4; mf++)
                ldsm4(af[mf], sa + ((wm + mf * 16 + a_r) * STR + kk * 8 + a_c) * 4);
#pragma unroll
            for (int p = 0; p < 2; p++) {
                uint32_t t4[4];
                ldsm4(t4, sB + ((wn + p * 16 + b_r) * STR + kk * 8 + b_c) * 4);
                bf[2 * p][0] = t4[0]; bf[2 * p][1] = t4[1];
                bf[2 * p + 1][0] = t4[2]; bf[2 * p + 1][1] = t4[3];
            }
#pragma unroll
            for (int mf = 0; mf < 4; mf++)
#pragma unroll
                for (int nf = 0; nf < 4; nf++)
                    mma16816(acc[mf][nf], af[mf], bf[nf]);
        }
    }

    const int r = lane >> 2, q = lane & 3;
#pragma unroll
    for (int mf = 0; mf < 4; mf++) {
        int rg = row0 + wm + mf * 16 + r;
#pragma unroll
        for (int nf = 0; nf < 4; nf++) {
            float* p0 = C + (size_t)rg * Ntot + col0 + wn + nf * 8 + q * 2;
            *(float2*)p0 = make_float2(acc[mf][nf][0], acc[mf][nf][1]);
            *(float2*)(p0 + (size_t)8 * Ntot) = make_float2(acc[mf][nf][2], acc[mf][nf][3]);
        }
    }
}

/* ---------------- fused layer-1: score + softmax + aggregate ----------------
   Block (256 thr) per dst node. Thread t owns cols 4t..4t+3 (head = t>>6).
   Per edge: one 4 KB read of xl[src] serves both score and numerator.      */
__global__ void __launch_bounds__(256)
k_fused1(const float* __restrict__ att, const float* __restrict__ bias)
{
    __shared__ float sred[2][8];
    const int n = blockIdx.x;
    const int tid = threadIdx.x;
    const int c0 = tid * 4;
    const int h = tid >> 6;
    const int w = tid >> 5;
    const int lane = tid & 31;

    const float4 xr = *(const float4*)&g_C1[(size_t)n * NT1 + 1024 + c0];
    const float4 at = *(const float4*)&att[c0];
    float num0 = 0.f, num1 = 0.f, num2 = 0.f, num3 = 0.f, den = 0.f;
    const int beg = g_offsets[n], end = g_offsets[n + 1];

    int par = 0;
    for (int j = beg; j < end; j++, par ^= 1) {
        int s = g_csr[j];
        float4 xl = *(const float4*)&g_C1[(size_t)s * NT1 + c0];
        float v0 = xl.x + xr.x, v1 = xl.y + xr.y, v2 = xl.z + xr.z, v3 = xl.w + xr.w;
        v0 = (v0 > 0.f) ? v0 : 0.2f * v0;
        v1 = (v1 > 0.f) ? v1 : 0.2f * v1;
        v2 = (v2 > 0.f) ? v2 : 0.2f * v2;
        v3 = (v3 > 0.f) ? v3 : 0.2f * v3;
        float p = fmaf(v0, at.x, fmaf(v1, at.y, fmaf(v2, at.z, v3 * at.w)));
#pragma unroll
        for (int o = 16; o > 0; o >>= 1)
            p += __shfl_xor_sync(0xffffffffu, p, o);
        if (lane == 0) sred[par][w] = p;
        __syncthreads();
        float ex = __expf(sred[par][2 * h] + sred[par][2 * h + 1]);
        den += ex;
        num0 = fmaf(ex, xl.x, num0);
        num1 = fmaf(ex, xl.y, num1);
        num2 = fmaf(ex, xl.z, num2);
        num3 = fmaf(ex, xl.w, num3);
    }

    const float4 b4 = *(const float4*)&bias[c0];
    float inv = 1.f / den;
    float r0 = fmaxf(fmaf(num0, inv, b4.x), 0.f);
    float r1 = fmaxf(fmaf(num1, inv, b4.y), 0.f);
    float r2 = fmaxf(fmaf(num2, inv, b4.z), 0.f);
    float r3 = fmaxf(fmaf(num3, inv, b4.w), 0.f);

    size_t base = (size_t)n * 2048 + c0;
    __nv_bfloat16 h0 = __float2bfloat16(r0), h1 = __float2bfloat16(r1);
    __nv_bfloat16 h2 = __float2bfloat16(r2), h3 = __float2bfloat16(r3);
    *(__nv_bfloat162*)&g_Ax2[base]     = __nv_bfloat162(h0, h1);
    *(__nv_bfloat162*)&g_Ax2[base + 2] = __nv_bfloat162(h2, h3);
    *(__nv_bfloat162*)&g_Ax2[base + 1024] = __nv_bfloat162(
        __float2bfloat16(r0 - __bfloat162float(h0)), __float2bfloat16(r1 - __bfloat162float(h1)));
    *(__nv_bfloat162*)&g_Ax2[base + 1026] = __nv_bfloat162(
        __float2bfloat16(r2 - __bfloat162float(h2)), __float2bfloat16(r3 - __bfloat162float(h3)));
}

/* ---------------- fused layer-2 (1 head, 256 cols): 64 threads/block ------ */
__global__ void __launch_bounds__(64)
k_fused2(const float* __restrict__ att, const float* __restrict__ bias,
         float* __restrict__ out)
{
    __shared__ float sred[2][2];
    const int n = blockIdx.x;
    const int tid = threadIdx.x;
    const int c0 = tid * 4;
    const int w = tid >> 5;
    const int lane = tid & 31;

    const float4 xr = *(const float4*)&g_C2[(size_t)n * NT2 + 256 + c0];
    const float4 at = *(const float4*)&att[c0];
    float num0 = 0.f, num1 = 0.f, num2 = 0.f, num3 = 0.f, den = 0.f;
    const int beg = g_offsets[n], end = g_offsets[n + 1];

    int par = 0;
    for (int j = beg; j < end; j++, par ^= 1) {
        int s = g_csr[j];
        float4 xl = *(const float4*)&g_C2[(size_t)s * NT2 + c0];
        float v0 = xl.x + xr.x, v1 = xl.y + xr.y, v2 = xl.z + xr.z, v3 = xl.w + xr.w;
        v0 = (v0 > 0.f) ? v0 : 0.2f * v0;
        v1 = (v1 > 0.f) ? v1 : 0.2f * v1;
        v2 = (v2 > 0.f) ? v2 : 0.2f * v2;
        v3 = (v3 > 0.f) ? v3 : 0.2f * v3;
        float p = fmaf(v0, at.x, fmaf(v1, at.y, fmaf(v2, at.z, v3 * at.w)));
#pragma unroll
        for (int o = 16; o > 0; o >>= 1)
            p += __shfl_xor_sync(0xffffffffu, p, o);
        if (lane == 0) sred[par][w] = p;
        __syncthreads();
        float ex = __expf(sred[par][0] + sred[par][1]);
        den += ex;
        num0 = fmaf(ex, xl.x, num0);
        num1 = fmaf(ex, xl.y, num1);
        num2 = fmaf(ex, xl.z, num2);
        num3 = fmaf(ex, xl.w, num3);
    }

    const float4 b4 = *(const float4*)&bias[c0];
    float inv = 1.f / den;
    float4 r;
    r.x = fmaxf(fmaf(num0, inv, b4.x), 0.f);
    r.y = fmaxf(fmaf(num1, inv, b4.y), 0.f);
    r.z = fmaxf(fmaf(num2, inv, b4.z), 0.f);
    r.w = fmaxf(fmaf(num3, inv, b4.w), 0.f);
    *(float4*)&out[(size_t)n * CC + c0] = r;
}

/* ---------------- launch ---------------- */
extern "C" void kernel_launch(void* const* d_in, const int* in_sizes, int n_in,
                              void* d_out, int out_size)
{
    const float* x    = (const float*)d_in[0];
    const int*   ei   = (const int*)  d_in[1];
    const float* Wl1  = (const float*)d_in[2];
    const float* Wr1  = (const float*)d_in[3];
    const float* att1 = (const float*)d_in[4];
    const float* b1   = (const float*)d_in[5];
    const float* Wl2  = (const float*)d_in[6];
    const float* Wr2  = (const float*)d_in[7];
    const float* att2 = (const float*)d_in[8];
    const float* b2   = (const float*)d_in[9];
    float* out = (float*)d_out;

    __nv_bfloat16 *p_Ax1, *p_Bt1, *p_Ax2, *p_Bt2;
    float *p_C1, *p_C2;
    cudaGetSymbolAddress((void**)&p_Ax1, g_Ax1);
    cudaGetSymbolAddress((void**)&p_Bt1, g_Bt1);
    cudaGetSymbolAddress((void**)&p_C1,  g_C1);
    cudaGetSymbolAddress((void**)&p_Ax2, g_Ax2);
    cudaGetSymbolAddress((void**)&p_Bt2, g_Bt2);
    cudaGetSymbolAddress((void**)&p_C2,  g_C2);

    cudaFuncSetAttribute(k_gemm_tc, cudaFuncAttributeMaxDynamicSharedMemorySize, GEMM_SMEM);

    /* CSR build + input splits */
    k_init_counts<<<NN / 256, 256>>>();
    k_count<<<EE / 256, 256>>>(ei);
    k_scan<<<1, 1024>>>();
    k_fill<<<ET / 256, 256>>>(ei);
    k_split_x<<<NN * K1 / 4 / 256, 256>>>(x);
    k_split_w<<<dim3(1024 / 32, K1 / 32), dim3(32, 8)>>>(Wl1, p_Bt1, 1024, 0);
    k_split_w<<<dim3(1024 / 32, K1 / 32), dim3(32, 8)>>>(Wr1, p_Bt1, 1024, 1024);
    k_split_w<<<dim3(256 / 32, K1 / 32),  dim3(32, 8)>>>(Wl2, p_Bt2, 256, 0);
    k_split_w<<<dim3(256 / 32, K1 / 32),  dim3(32, 8)>>>(Wr2, p_Bt2, 256, 256);

    /* layer 1 */
    k_gemm_tc<<<dim3(NT1 / BN, NN / BM), 256, GEMM_SMEM>>>(p_Ax1, p_Bt1, p_C1, NT1);
    k_fused1<<<NN, 256>>>(att1, b1);

    /* layer 2 */
    k_gemm_tc<<<dim3(NT2 / BN, NN / BM), 256, GEMM_SMEM>>>(p_Ax2, p_Bt2, p_C2, NT2);
    k_fused2<<<NN, 64>>>(att2, b2, out);
}